// round 1
// baseline (speedup 1.0000x reference)
#include <cuda_runtime.h>
#include <math_constants.h>

#define B_  8
#define S_  2048
#define D_  512
#define H_  8
#define DH_ 64
#define M_  (B_*S_)   // 16384

// Scratch (allocation-free rule: __device__ globals)
__device__ float g_Q[B_*H_*S_*DH_];
__device__ float g_K[B_*H_*S_*DH_];
__device__ float g_V[B_*H_*S_*DH_];
__device__ float g_O[M_*D_];

// ---------------------------------------------------------------------------
// QKV projection: X[16384,512] @ W^T[512,1536] + b  -> scatter to Q,K,V [B,H,S,Dh]
// 128x128x8 tile, 8x8 microtile, 256 threads. Q scaled by 1/sqrt(Dh)=0.125.
// ---------------------------------------------------------------------------
__global__ __launch_bounds__(256) void qkv_kernel(const float* __restrict__ X,
                                                  const float* __restrict__ W,
                                                  const float* __restrict__ bias) {
    __shared__ float As[8][128];
    __shared__ float Bs[8][128];
    const int K = D_;
    int tid = threadIdx.x;
    int m0 = blockIdx.y * 128;
    int n0 = blockIdx.x * 128;
    int lr = tid >> 1;
    int lc = (tid & 1) << 2;
    const float* Ap = X + (size_t)(m0 + lr) * K + lc;
    const float* Bp = W + (size_t)(n0 + lr) * K + lc;
    int ty = tid >> 4, tx = tid & 15;

    float acc[8][8];
#pragma unroll
    for (int i = 0; i < 8; i++)
#pragma unroll
        for (int j = 0; j < 8; j++) acc[i][j] = 0.f;

    for (int k0 = 0; k0 < K; k0 += 8) {
        float4 av = *(const float4*)(Ap + k0);
        float4 bv = *(const float4*)(Bp + k0);
        As[lc+0][lr] = av.x; As[lc+1][lr] = av.y; As[lc+2][lr] = av.z; As[lc+3][lr] = av.w;
        Bs[lc+0][lr] = bv.x; Bs[lc+1][lr] = bv.y; Bs[lc+2][lr] = bv.z; Bs[lc+3][lr] = bv.w;
        __syncthreads();
#pragma unroll
        for (int kk = 0; kk < 8; kk++) {
            float a[8], b[8];
            *(float4*)&a[0] = *(const float4*)&As[kk][ty*8];
            *(float4*)&a[4] = *(const float4*)&As[kk][ty*8+4];
            *(float4*)&b[0] = *(const float4*)&Bs[kk][tx*8];
            *(float4*)&b[4] = *(const float4*)&Bs[kk][tx*8+4];
#pragma unroll
            for (int i = 0; i < 8; i++)
#pragma unroll
                for (int j = 0; j < 8; j++)
                    acc[i][j] += a[i] * b[j];
        }
        __syncthreads();
    }

    // Whole 128-wide block sits inside one of the q/k/v sections (512-wide).
    int sec = n0 >> 9;
    float* dst = (sec == 0) ? g_Q : (sec == 1 ? g_K : g_V);
    float qscale = (sec == 0) ? 0.125f : 1.0f;
#pragma unroll
    for (int i = 0; i < 8; i++) {
        int mm = m0 + ty*8 + i;
        int bb = mm >> 11, ss = mm & (S_ - 1);
#pragma unroll
        for (int j = 0; j < 8; j++) {
            int n = n0 + tx*8 + j;
            int d = n & (D_ - 1);
            int hh = d >> 6, dh = d & 63;
            float v = (acc[i][j] + bias[n]) * qscale;
            dst[(((size_t)(bb*H_ + hh))*S_ + ss)*DH_ + dh] = v;
        }
    }
}

// ---------------------------------------------------------------------------
// Flash attention: one CTA per (b, h, 64-query tile). 64-key tiles.
// Qs/Ks stored feature-major [d][r] with XOR-4 swizzle; K and V share a
// buffer so static smem = 3 * 16KB = 48KB exactly.
// Q already carries the 1/sqrt(Dh) scale.
// ---------------------------------------------------------------------------
__device__ __forceinline__ int swz(int d, int c) {
    return d*64 + ((((c >> 2) ^ d) & 15) << 2) + (c & 3);
}

__global__ __launch_bounds__(256) void attn_kernel() {
    __shared__ float Qs[64*64];
    __shared__ float KVs[64*64];
    __shared__ float Ps[64*64];

    int qt = blockIdx.x, h = blockIdx.y, b = blockIdx.z;
    const float* Qg = g_Q + (((size_t)(b*H_ + h))*S_ + qt*64) * DH_;
    const float* Kg = g_K + ((size_t)(b*H_ + h))*S_ * DH_;
    const float* Vg = g_V + ((size_t)(b*H_ + h))*S_ * DH_;

    int tid = threadIdx.x;
    int ty = tid >> 4, tx = tid & 15;
    int r0 = ty*4, c0 = tx*4;

    // Load Q tile transposed + swizzled: Qs[d][r] = Q[r][d]
    for (int i = tid; i < 64*64; i += 256) {
        int r = i >> 6, d = i & 63;
        Qs[swz(d, r)] = Qg[i];
    }

    float m[4], l[4], acc[4][4];
#pragma unroll
    for (int i = 0; i < 4; i++) {
        m[i] = -CUDART_INF_F;
        l[i] = 0.f;
#pragma unroll
        for (int j = 0; j < 4; j++) acc[i][j] = 0.f;
    }
    __syncthreads();

    for (int kt = 0; kt < S_/64; kt++) {
        // Load K tile transposed + swizzled: KVs[d][c] = K[c][d]
        const float* Kt = Kg + (size_t)kt * 64 * DH_;
        for (int i = tid; i < 64*64; i += 256) {
            int c = i >> 6, d = i & 63;
            KVs[swz(d, c)] = Kt[i];
        }
        __syncthreads();

        // S = Q K^T (thread owns 4x4 of the 64x64 score tile)
        float s[4][4];
#pragma unroll
        for (int i = 0; i < 4; i++)
#pragma unroll
            for (int j = 0; j < 4; j++) s[i][j] = 0.f;

#pragma unroll 16
        for (int d = 0; d < 64; d++) {
            float4 qv = *(const float4*)&Qs[d*64 + (((ty ^ d) & 15) << 2)];
            float4 kv = *(const float4*)&KVs[d*64 + (((tx ^ d) & 15) << 2)];
            s[0][0] += qv.x*kv.x; s[0][1] += qv.x*kv.y; s[0][2] += qv.x*kv.z; s[0][3] += qv.x*kv.w;
            s[1][0] += qv.y*kv.x; s[1][1] += qv.y*kv.y; s[1][2] += qv.y*kv.z; s[1][3] += qv.y*kv.w;
            s[2][0] += qv.z*kv.x; s[2][1] += qv.z*kv.y; s[2][2] += qv.z*kv.z; s[2][3] += qv.z*kv.w;
            s[3][0] += qv.w*kv.x; s[3][1] += qv.w*kv.y; s[3][2] += qv.w*kv.z; s[3][3] += qv.w*kv.w;
        }

        // Online softmax (row reduction across tx = low 4 lane bits)
#pragma unroll
        for (int i = 0; i < 4; i++) {
            float mx = fmaxf(fmaxf(s[i][0], s[i][1]), fmaxf(s[i][2], s[i][3]));
#pragma unroll
            for (int o = 8; o >= 1; o >>= 1)
                mx = fmaxf(mx, __shfl_xor_sync(0xffffffffu, mx, o));
            float mnew = fmaxf(m[i], mx);
            float alpha = __expf(m[i] - mnew);   // first iter: exp(-inf)=0
            m[i] = mnew;
            float rs = 0.f;
#pragma unroll
            for (int j = 0; j < 4; j++) { s[i][j] = __expf(s[i][j] - mnew); rs += s[i][j]; }
#pragma unroll
            for (int o = 8; o >= 1; o >>= 1)
                rs += __shfl_xor_sync(0xffffffffu, rs, o);
            l[i] = l[i]*alpha + rs;
#pragma unroll
            for (int j = 0; j < 4; j++) acc[i][j] *= alpha;
        }
        __syncthreads();   // everyone done reading KVs (K) and Ps (prev iter)

        // Publish P tile; reload KVs with V (natural [k][d] layout)
#pragma unroll
        for (int i = 0; i < 4; i++) {
            float4 pv = make_float4(s[i][0], s[i][1], s[i][2], s[i][3]);
            *(float4*)&Ps[(r0+i)*64 + c0] = pv;
        }
        const float* Vt = Vg + (size_t)kt * 64 * DH_;
        for (int i = tid; i < 64*64; i += 256) {
            KVs[i] = Vt[i];
        }
        __syncthreads();

        // O += P V
#pragma unroll 8
        for (int k = 0; k < 64; k++) {
            float4 vv = *(const float4*)&KVs[k*64 + c0];
#pragma unroll
            for (int i = 0; i < 4; i++) {
                float p = Ps[(r0+i)*64 + k];
                acc[i][0] += p*vv.x; acc[i][1] += p*vv.y;
                acc[i][2] += p*vv.z; acc[i][3] += p*vv.w;
            }
        }
        __syncthreads();   // before next iter overwrites KVs
    }

    // Normalize and write to g_O in (B, S, H*Dh) layout
    float* Og = g_O + ((size_t)(b*S_ + qt*64))*D_ + h*DH_;
#pragma unroll
    for (int i = 0; i < 4; i++) {
        float inv = 1.0f / l[i];
        float4 o = make_float4(acc[i][0]*inv, acc[i][1]*inv, acc[i][2]*inv, acc[i][3]*inv);
        *(float4*)&Og[(size_t)(r0+i)*D_ + c0] = o;
    }
}

// ---------------------------------------------------------------------------
// Output projection: g_O[16384,512] @ w_out^T + b_out -> out
// ---------------------------------------------------------------------------
__global__ __launch_bounds__(256) void out_kernel(const float* __restrict__ W,
                                                  const float* __restrict__ bias,
                                                  float* __restrict__ out) {
    __shared__ float As[8][128];
    __shared__ float Bs[8][128];
    const int K = D_;
    int tid = threadIdx.x;
    int m0 = blockIdx.y * 128;
    int n0 = blockIdx.x * 128;
    int lr = tid >> 1;
    int lc = (tid & 1) << 2;
    const float* Ap = g_O + (size_t)(m0 + lr) * K + lc;
    const float* Bp = W + (size_t)(n0 + lr) * K + lc;
    int ty = tid >> 4, tx = tid & 15;

    float acc[8][8];
#pragma unroll
    for (int i = 0; i < 8; i++)
#pragma unroll
        for (int j = 0; j < 8; j++) acc[i][j] = 0.f;

    for (int k0 = 0; k0 < K; k0 += 8) {
        float4 av = *(const float4*)(Ap + k0);
        float4 bv = *(const float4*)(Bp + k0);
        As[lc+0][lr] = av.x; As[lc+1][lr] = av.y; As[lc+2][lr] = av.z; As[lc+3][lr] = av.w;
        Bs[lc+0][lr] = bv.x; Bs[lc+1][lr] = bv.y; Bs[lc+2][lr] = bv.z; Bs[lc+3][lr] = bv.w;
        __syncthreads();
#pragma unroll
        for (int kk = 0; kk < 8; kk++) {
            float a[8], b[8];
            *(float4*)&a[0] = *(const float4*)&As[kk][ty*8];
            *(float4*)&a[4] = *(const float4*)&As[kk][ty*8+4];
            *(float4*)&b[0] = *(const float4*)&Bs[kk][tx*8];
            *(float4*)&b[4] = *(const float4*)&Bs[kk][tx*8+4];
#pragma unroll
            for (int i = 0; i < 8; i++)
#pragma unroll
                for (int j = 0; j < 8; j++)
                    acc[i][j] += a[i] * b[j];
        }
        __syncthreads();
    }

#pragma unroll
    for (int i = 0; i < 8; i++) {
        int mm = m0 + ty*8 + i;
#pragma unroll
        for (int j = 0; j < 8; j++) {
            int n = n0 + tx*8 + j;
            out[(size_t)mm * D_ + n] = acc[i][j] + bias[n];
        }
    }
}

// ---------------------------------------------------------------------------
extern "C" void kernel_launch(void* const* d_in, const int* in_sizes, int n_in,
                              void* d_out, int out_size) {
    const float* x     = (const float*)d_in[0];
    const float* w_in  = (const float*)d_in[1];
    const float* b_in  = (const float*)d_in[2];
    const float* w_out = (const float*)d_in[3];
    const float* b_out = (const float*)d_in[4];
    float* out = (float*)d_out;

    qkv_kernel<<<dim3(12, 128), 256>>>(x, w_in, b_in);          // N=1536
    attn_kernel<<<dim3(S_/64, H_, B_), 256>>>();                // 2048 CTAs
    out_kernel<<<dim3(4, 128), 256>>>(w_out, b_out, out);       // N=512
}

// round 2
// speedup vs baseline: 3.0245x; 3.0245x over previous
#include <cuda_runtime.h>
#include <math_constants.h>

#define B_  8
#define S_  2048
#define D_  512
#define H_  8
#define DH_ 64
#define M_  (B_*S_)   // 16384

// Scratch (allocation-free rule: __device__ globals)
__device__ float g_Q[B_*H_*S_*DH_];
__device__ float g_K[B_*H_*S_*DH_];
__device__ float g_V[B_*H_*S_*DH_];
__device__ float g_O[M_*D_];

// ---------------------------------------------------------------------------
// tf32 helpers
// ---------------------------------------------------------------------------
__device__ __forceinline__ unsigned tf32u(float x) {
    unsigned u;
    asm("cvt.rna.tf32.f32 %0, %1;" : "=r"(u) : "f"(x));
    return u;
}
__device__ __forceinline__ float tf32f(float x) {
    return __uint_as_float(tf32u(x));
}
__device__ __forceinline__ unsigned fu(float x) { return __float_as_uint(x); }

// D = A(16x8 tf32, row) * B(8x8 tf32, col) + D, fp32 accumulate
__device__ __forceinline__ void mma8(float* c, const unsigned* a, const unsigned* b) {
    asm volatile(
        "mma.sync.aligned.m16n8k8.row.col.f32.tf32.tf32.f32 "
        "{%0,%1,%2,%3}, {%4,%5,%6,%7}, {%8,%9}, {%0,%1,%2,%3};"
        : "+f"(c[0]), "+f"(c[1]), "+f"(c[2]), "+f"(c[3])
        : "r"(a[0]), "r"(a[1]), "r"(a[2]), "r"(a[3]), "r"(b[0]), "r"(b[1]));
}

// ---------------------------------------------------------------------------
// QKV projection: X[16384,512] @ W^T + b -> scatter tf32-rounded to Q,K,V
// CTA 128x128, 256 threads (8 warps, 4x2), k-chunk 32. Q scaled by 0.125.
// ---------------------------------------------------------------------------
#define GP 36   // smem row pad (floats)

__global__ __launch_bounds__(256) void qkv_kernel(const float* __restrict__ X,
                                                  const float* __restrict__ W,
                                                  const float* __restrict__ bias) {
    __shared__ float As[128 * GP];
    __shared__ float Bs[128 * GP];
    int tid = threadIdx.x;
    int m0 = blockIdx.y * 128, n0 = blockIdx.x * 128;
    int w = tid >> 5, lane = tid & 31;
    int wm = w >> 1, wn = w & 1;
    int g = lane >> 2, tg = lane & 3;
    int lr = tid >> 3;            // 0..31
    int lc4 = (tid & 7) * 4;      // 0..28

    float acc[2][8][4];
#pragma unroll
    for (int mt = 0; mt < 2; mt++)
#pragma unroll
        for (int nt = 0; nt < 8; nt++)
#pragma unroll
            for (int i = 0; i < 4; i++) acc[mt][nt][i] = 0.f;

    for (int kc = 0; kc < D_; kc += 32) {
#pragma unroll
        for (int p = 0; p < 4; p++) {
            int row = lr + p * 32;
            float4 a = *(const float4*)(X + (size_t)(m0 + row) * D_ + kc + lc4);
            float4 b = *(const float4*)(W + (size_t)(n0 + row) * D_ + kc + lc4);
            As[row * GP + lc4 + 0] = tf32f(a.x); As[row * GP + lc4 + 1] = tf32f(a.y);
            As[row * GP + lc4 + 2] = tf32f(a.z); As[row * GP + lc4 + 3] = tf32f(a.w);
            Bs[row * GP + lc4 + 0] = tf32f(b.x); Bs[row * GP + lc4 + 1] = tf32f(b.y);
            Bs[row * GP + lc4 + 2] = tf32f(b.z); Bs[row * GP + lc4 + 3] = tf32f(b.w);
        }
        __syncthreads();
#pragma unroll
        for (int ks = 0; ks < 4; ks++) {
            int kb = ks * 8;
            unsigned a[2][4];
#pragma unroll
            for (int mt = 0; mt < 2; mt++) {
                int r = wm * 32 + mt * 16 + g;
                a[mt][0] = fu(As[r * GP + kb + tg]);
                a[mt][1] = fu(As[(r + 8) * GP + kb + tg]);
                a[mt][2] = fu(As[r * GP + kb + tg + 4]);
                a[mt][3] = fu(As[(r + 8) * GP + kb + tg + 4]);
            }
#pragma unroll
            for (int nt = 0; nt < 8; nt++) {
                int c = wn * 64 + nt * 8 + g;
                unsigned b[2];
                b[0] = fu(Bs[c * GP + kb + tg]);
                b[1] = fu(Bs[c * GP + kb + tg + 4]);
                mma8(acc[0][nt], a[0], b);
                mma8(acc[1][nt], a[1], b);
            }
        }
        __syncthreads();
    }

    int sec = n0 >> 9;
    float* dst = (sec == 0) ? g_Q : (sec == 1 ? g_K : g_V);
    float qs = (sec == 0) ? 0.125f : 1.0f;
#pragma unroll
    for (int mt = 0; mt < 2; mt++) {
#pragma unroll
        for (int half = 0; half < 2; half++) {
            int mm = m0 + wm * 32 + mt * 16 + g + half * 8;
            int bb = mm >> 11, ss = mm & (S_ - 1);
#pragma unroll
            for (int nt = 0; nt < 8; nt++) {
                int col = n0 + wn * 64 + nt * 8 + 2 * tg;
                float2 bi = *(const float2*)(bias + col);
                float v0 = tf32f((acc[mt][nt][half * 2 + 0] + bi.x) * qs);
                float v1 = tf32f((acc[mt][nt][half * 2 + 1] + bi.y) * qs);
                int d = col & (D_ - 1);
                int hh = d >> 6, dh = d & 63;
                float* p = dst + (((size_t)(bb * H_ + hh)) * S_ + ss) * DH_ + dh;
                *(float2*)p = make_float2(v0, v1);
            }
        }
    }
}

// ---------------------------------------------------------------------------
// Flash attention with tf32 mma. CTA = (b, h, 64-q tile), 128 threads (4 warps,
// each owns 16 q rows). Key tiles of 64. Q frags cached in registers; SP smem
// buffer holds Q during prologue then per-warp P tiles; KV holds K then V.
// ---------------------------------------------------------------------------
#define QP 68
#define VP 72

__global__ __launch_bounds__(128) void attn_kernel() {
    __shared__ float SP[64 * QP];
    __shared__ float KV[64 * VP];

    int qt = blockIdx.x, h = blockIdx.y, b = blockIdx.z;
    const float* Qg = g_Q + (((size_t)(b * H_ + h)) * S_ + qt * 64) * DH_;
    const float* Kg = g_K + ((size_t)(b * H_ + h)) * S_ * DH_;
    const float* Vg = g_V + ((size_t)(b * H_ + h)) * S_ * DH_;

    int tid = threadIdx.x, w = tid >> 5, lane = tid & 31;
    int g = lane >> 2, tg = lane & 3;
    int lrow = tid >> 4, lc4 = (tid & 15) * 4;
    int r0 = w * 16;

    // Load Q tile into SP
#pragma unroll
    for (int p = 0; p < 8; p++) {
        int row = lrow + p * 8;
        *(float4*)&SP[row * QP + lc4] = *(const float4*)(Qg + row * DH_ + lc4);
    }
    __syncthreads();

    // Q A-fragments for all 8 k-steps (d = 64)
    unsigned qf[8][4];
#pragma unroll
    for (int ks = 0; ks < 8; ks++) {
        qf[ks][0] = fu(SP[(r0 + g) * QP + ks * 8 + tg]);
        qf[ks][1] = fu(SP[(r0 + g + 8) * QP + ks * 8 + tg]);
        qf[ks][2] = fu(SP[(r0 + g) * QP + ks * 8 + tg + 4]);
        qf[ks][3] = fu(SP[(r0 + g + 8) * QP + ks * 8 + tg + 4]);
    }

    float oacc[8][4];
#pragma unroll
    for (int dt = 0; dt < 8; dt++)
#pragma unroll
        for (int i = 0; i < 4; i++) oacc[dt][i] = 0.f;
    float ml = -CUDART_INF_F, mh = -CUDART_INF_F, ll = 0.f, lh = 0.f;

    for (int kt = 0; kt < S_ / 64; kt++) {
        __syncthreads();   // prev iter PV readers done with KV
        const float* Kt = Kg + (size_t)kt * 64 * DH_;
#pragma unroll
        for (int p = 0; p < 8; p++) {
            int row = lrow + p * 8;
            *(float4*)&KV[row * VP + lc4] = *(const float4*)(Kt + row * DH_ + lc4);
        }
        __syncthreads();

        // S = Q K^T
        float s[8][4];
#pragma unroll
        for (int nt = 0; nt < 8; nt++)
#pragma unroll
            for (int i = 0; i < 4; i++) s[nt][i] = 0.f;
#pragma unroll
        for (int ks = 0; ks < 8; ks++) {
            int kb = ks * 8;
#pragma unroll
            for (int nt = 0; nt < 8; nt++) {
                int n = nt * 8 + g;
                unsigned bb[2];
                bb[0] = fu(KV[n * VP + kb + tg]);
                bb[1] = fu(KV[n * VP + kb + tg + 4]);
                mma8(s[nt], qf[ks], bb);
            }
        }

        // online softmax (rows rlow = r0+g, rhigh = r0+g+8; row spread over lane%4)
        float mxl = -CUDART_INF_F, mxh = -CUDART_INF_F;
#pragma unroll
        for (int nt = 0; nt < 8; nt++) {
            mxl = fmaxf(mxl, fmaxf(s[nt][0], s[nt][1]));
            mxh = fmaxf(mxh, fmaxf(s[nt][2], s[nt][3]));
        }
        mxl = fmaxf(mxl, __shfl_xor_sync(0xffffffffu, mxl, 1));
        mxl = fmaxf(mxl, __shfl_xor_sync(0xffffffffu, mxl, 2));
        mxh = fmaxf(mxh, __shfl_xor_sync(0xffffffffu, mxh, 1));
        mxh = fmaxf(mxh, __shfl_xor_sync(0xffffffffu, mxh, 2));
        float mnl = fmaxf(ml, mxl), mnh = fmaxf(mh, mxh);
        float al = __expf(ml - mnl), ah = __expf(mh - mnh);
        ml = mnl; mh = mnh;
        float rsl = 0.f, rsh = 0.f;
#pragma unroll
        for (int nt = 0; nt < 8; nt++) {
            s[nt][0] = __expf(s[nt][0] - mnl);
            s[nt][1] = __expf(s[nt][1] - mnl);
            s[nt][2] = __expf(s[nt][2] - mnh);
            s[nt][3] = __expf(s[nt][3] - mnh);
            rsl += s[nt][0] + s[nt][1];
            rsh += s[nt][2] + s[nt][3];
        }
        rsl += __shfl_xor_sync(0xffffffffu, rsl, 1);
        rsl += __shfl_xor_sync(0xffffffffu, rsl, 2);
        rsh += __shfl_xor_sync(0xffffffffu, rsh, 1);
        rsh += __shfl_xor_sync(0xffffffffu, rsh, 2);
        ll = ll * al + rsl; lh = lh * ah + rsh;
#pragma unroll
        for (int dt = 0; dt < 8; dt++) {
            oacc[dt][0] *= al; oacc[dt][1] *= al;
            oacc[dt][2] *= ah; oacc[dt][3] *= ah;
        }
        __syncthreads();   // all warps done reading KV as K

        // load V tile into KV; store P (own warp rows) into SP
        const float* Vt = Vg + (size_t)kt * 64 * DH_;
#pragma unroll
        for (int p = 0; p < 8; p++) {
            int row = lrow + p * 8;
            *(float4*)&KV[row * VP + lc4] = *(const float4*)(Vt + row * DH_ + lc4);
        }
        int rl = r0 + g, rh = rl + 8;
#pragma unroll
        for (int nt = 0; nt < 8; nt++) {
            int c = nt * 8 + 2 * tg;
            SP[rl * QP + c]     = tf32f(s[nt][0]);
            SP[rl * QP + c + 1] = tf32f(s[nt][1]);
            SP[rh * QP + c]     = tf32f(s[nt][2]);
            SP[rh * QP + c + 1] = tf32f(s[nt][3]);
        }
        __syncthreads();   // V ready + P visible

        // O += P V
#pragma unroll
        for (int ks = 0; ks < 8; ks++) {
            int kb = ks * 8;
            unsigned pa[4];
            pa[0] = fu(SP[(r0 + g) * QP + kb + tg]);
            pa[1] = fu(SP[(r0 + g + 8) * QP + kb + tg]);
            pa[2] = fu(SP[(r0 + g) * QP + kb + tg + 4]);
            pa[3] = fu(SP[(r0 + g + 8) * QP + kb + tg + 4]);
#pragma unroll
            for (int dt = 0; dt < 8; dt++) {
                unsigned bb[2];
                bb[0] = fu(KV[(kb + tg) * VP + dt * 8 + g]);
                bb[1] = fu(KV[(kb + tg + 4) * VP + dt * 8 + g]);
                mma8(oacc[dt], pa, bb);
            }
        }
    }

    // epilogue: normalize and write to g_O (B, S, H*Dh), tf32-rounded
    float il = 1.0f / ll, ih = 1.0f / lh;
    float* Og = g_O + ((size_t)(b * S_ + qt * 64)) * D_ + h * DH_;
    int rl = r0 + g, rh = rl + 8;
#pragma unroll
    for (int dt = 0; dt < 8; dt++) {
        int c = dt * 8 + 2 * tg;
        *(float2*)&Og[(size_t)rl * D_ + c] =
            make_float2(tf32f(oacc[dt][0] * il), tf32f(oacc[dt][1] * il));
        *(float2*)&Og[(size_t)rh * D_ + c] =
            make_float2(tf32f(oacc[dt][2] * ih), tf32f(oacc[dt][3] * ih));
    }
}

// ---------------------------------------------------------------------------
// Output projection: g_O[16384,512] @ w_out^T + b_out -> out (fp32 result)
// ---------------------------------------------------------------------------
__global__ __launch_bounds__(256) void out_kernel(const float* __restrict__ W,
                                                  const float* __restrict__ bias,
                                                  float* __restrict__ out) {
    __shared__ float As[128 * GP];
    __shared__ float Bs[128 * GP];
    int tid = threadIdx.x;
    int m0 = blockIdx.y * 128, n0 = blockIdx.x * 128;
    int w = tid >> 5, lane = tid & 31;
    int wm = w >> 1, wn = w & 1;
    int g = lane >> 2, tg = lane & 3;
    int lr = tid >> 3;
    int lc4 = (tid & 7) * 4;

    float acc[2][8][4];
#pragma unroll
    for (int mt = 0; mt < 2; mt++)
#pragma unroll
        for (int nt = 0; nt < 8; nt++)
#pragma unroll
            for (int i = 0; i < 4; i++) acc[mt][nt][i] = 0.f;

    for (int kc = 0; kc < D_; kc += 32) {
#pragma unroll
        for (int p = 0; p < 4; p++) {
            int row = lr + p * 32;
            float4 a = *(const float4*)(g_O + (size_t)(m0 + row) * D_ + kc + lc4);
            float4 b = *(const float4*)(W + (size_t)(n0 + row) * D_ + kc + lc4);
            As[row * GP + lc4 + 0] = a.x; As[row * GP + lc4 + 1] = a.y;   // already tf32
            As[row * GP + lc4 + 2] = a.z; As[row * GP + lc4 + 3] = a.w;
            Bs[row * GP + lc4 + 0] = tf32f(b.x); Bs[row * GP + lc4 + 1] = tf32f(b.y);
            Bs[row * GP + lc4 + 2] = tf32f(b.z); Bs[row * GP + lc4 + 3] = tf32f(b.w);
        }
        __syncthreads();
#pragma unroll
        for (int ks = 0; ks < 4; ks++) {
            int kb = ks * 8;
            unsigned a[2][4];
#pragma unroll
            for (int mt = 0; mt < 2; mt++) {
                int r = wm * 32 + mt * 16 + g;
                a[mt][0] = fu(As[r * GP + kb + tg]);
                a[mt][1] = fu(As[(r + 8) * GP + kb + tg]);
                a[mt][2] = fu(As[r * GP + kb + tg + 4]);
                a[mt][3] = fu(As[(r + 8) * GP + kb + tg + 4]);
            }
#pragma unroll
            for (int nt = 0; nt < 8; nt++) {
                int c = wn * 64 + nt * 8 + g;
                unsigned b[2];
                b[0] = fu(Bs[c * GP + kb + tg]);
                b[1] = fu(Bs[c * GP + kb + tg + 4]);
                mma8(acc[0][nt], a[0], b);
                mma8(acc[1][nt], a[1], b);
            }
        }
        __syncthreads();
    }

#pragma unroll
    for (int mt = 0; mt < 2; mt++) {
#pragma unroll
        for (int half = 0; half < 2; half++) {
            int mm = m0 + wm * 32 + mt * 16 + g + half * 8;
#pragma unroll
            for (int nt = 0; nt < 8; nt++) {
                int col = n0 + wn * 64 + nt * 8 + 2 * tg;
                float2 bi = *(const float2*)(bias + col);
                *(float2*)&out[(size_t)mm * D_ + col] =
                    make_float2(acc[mt][nt][half * 2 + 0] + bi.x,
                                acc[mt][nt][half * 2 + 1] + bi.y);
            }
        }
    }
}

// ---------------------------------------------------------------------------
extern "C" void kernel_launch(void* const* d_in, const int* in_sizes, int n_in,
                              void* d_out, int out_size) {
    const float* x     = (const float*)d_in[0];
    const float* w_in  = (const float*)d_in[1];
    const float* b_in  = (const float*)d_in[2];
    const float* w_out = (const float*)d_in[3];
    const float* b_out = (const float*)d_in[4];
    float* out = (float*)d_out;

    qkv_kernel<<<dim3(12, 128), 256>>>(x, w_in, b_in);       // N=1536
    attn_kernel<<<dim3(S_ / 64, H_, B_), 128>>>();           // 2048 CTAs
    out_kernel<<<dim3(4, 128), 256>>>(w_out, b_out, out);    // N=512
}

// round 3
// speedup vs baseline: 4.0218x; 1.3297x over previous
#include <cuda_runtime.h>
#include <math_constants.h>

#define B_  8
#define S_  2048
#define D_  512
#define H_  8
#define DH_ 64
#define M_  (B_*S_)   // 16384
#define NT_ (S_/64)   // 32 key tiles

// Scratch (allocation-free rule: __device__ globals)
__device__ float g_Q[B_*H_*S_*DH_];
__device__ float g_K[B_*H_*S_*DH_];
__device__ float g_V[B_*H_*S_*DH_];
__device__ float g_O[M_*D_];
__device__ float g_X[M_*D_];        // tf32-rounded x
__device__ float g_Wi[3*D_*D_];     // tf32-rounded w_in
__device__ float g_Wo[D_*D_];       // tf32-rounded w_out

// ---------------------------------------------------------------------------
// helpers
// ---------------------------------------------------------------------------
__device__ __forceinline__ unsigned tf32u(float x) {
    unsigned u;
    asm("cvt.rna.tf32.f32 %0, %1;" : "=r"(u) : "f"(x));
    return u;
}
__device__ __forceinline__ float tf32f(float x) { return __uint_as_float(tf32u(x)); }
__device__ __forceinline__ unsigned fu(float x) { return __float_as_uint(x); }

__device__ __forceinline__ void mma8(float* c, const unsigned* a, const unsigned* b) {
    asm volatile(
        "mma.sync.aligned.m16n8k8.row.col.f32.tf32.tf32.f32 "
        "{%0,%1,%2,%3}, {%4,%5,%6,%7}, {%8,%9}, {%0,%1,%2,%3};"
        : "+f"(c[0]), "+f"(c[1]), "+f"(c[2]), "+f"(c[3])
        : "r"(a[0]), "r"(a[1]), "r"(a[2]), "r"(a[3]), "r"(b[0]), "r"(b[1]));
}

__device__ __forceinline__ unsigned sptr(const void* p) {
    return (unsigned)__cvta_generic_to_shared(p);
}
#define CP16(d, s)  asm volatile("cp.async.cg.shared.global [%0], [%1], 16;\n" :: "r"(d), "l"(s))
#define CPCOMMIT    asm volatile("cp.async.commit_group;\n")
#define CPWAIT1     asm volatile("cp.async.wait_group 1;\n")
#define CPWAIT0     asm volatile("cp.async.wait_group 0;\n")

// ---------------------------------------------------------------------------
// tf32 pre-round (elementwise, float4)
// ---------------------------------------------------------------------------
__global__ void round_kernel(const float4* __restrict__ in, float4* __restrict__ out, int n4) {
    int i = blockIdx.x * 256 + threadIdx.x;
    if (i < n4) {
        float4 v = in[i];
        out[i] = make_float4(tf32f(v.x), tf32f(v.y), tf32f(v.z), tf32f(v.w));
    }
}

// ---------------------------------------------------------------------------
// QKV projection: g_X[16384,512] @ g_Wi^T + b -> scatter tf32-rounded to Q,K,V
// 128x128 tile, 256 threads, k-chunk 32, 2-stage cp.async pipeline. pitch 36.
// ---------------------------------------------------------------------------
#define GP 36
#define GST (128*GP)   // 4608 floats per stage

__global__ __launch_bounds__(256, 2) void qkv_kernel(const float* __restrict__ bias) {
    extern __shared__ float sm[];
    float* As = sm;              // 2 stages
    float* Bs = sm + 2*GST;

    int tid = threadIdx.x;
    int m0 = blockIdx.y * 128, n0 = blockIdx.x * 128;
    int w = tid >> 5, lane = tid & 31;
    int wm = w >> 1, wn = w & 1;
    int g = lane >> 2, tg = lane & 3;
    int lr = tid >> 3, lc4 = (tid & 7) * 4;

    const float* X = g_X;
    const float* W = g_Wi;

    // stage issue: A,B tiles of 128x32 from column kc
#define QKV_ISSUE(kc, stg) do {                                               \
        _Pragma("unroll")                                                     \
        for (int p = 0; p < 4; p++) {                                         \
            int row = lr + p * 32;                                            \
            CP16(sptr(&As[(stg)*GST + row*GP + lc4]),                         \
                 X + (size_t)(m0 + row) * D_ + (kc) + lc4);                   \
            CP16(sptr(&Bs[(stg)*GST + row*GP + lc4]),                         \
                 W + (size_t)(n0 + row) * D_ + (kc) + lc4);                   \
        }                                                                     \
        CPCOMMIT;                                                             \
    } while (0)

    QKV_ISSUE(0, 0);

    float acc[2][8][4];
#pragma unroll
    for (int mt = 0; mt < 2; mt++)
#pragma unroll
        for (int nt = 0; nt < 8; nt++)
#pragma unroll
            for (int i = 0; i < 4; i++) acc[mt][nt][i] = 0.f;

    for (int kci = 0; kci < 16; kci++) {
        int cur = kci & 1;
        if (kci + 1 < 16) { QKV_ISSUE((kci + 1) * 32, cur ^ 1); CPWAIT1; }
        else              { CPWAIT0; }
        __syncthreads();
        const float* A = As + cur * GST;
        const float* B = Bs + cur * GST;
#pragma unroll
        for (int ks = 0; ks < 4; ks++) {
            int kb = ks * 8;
            unsigned a[2][4];
#pragma unroll
            for (int mt = 0; mt < 2; mt++) {
                int r = wm * 32 + mt * 16 + g;
                a[mt][0] = fu(A[r * GP + kb + tg]);
                a[mt][1] = fu(A[(r + 8) * GP + kb + tg]);
                a[mt][2] = fu(A[r * GP + kb + tg + 4]);
                a[mt][3] = fu(A[(r + 8) * GP + kb + tg + 4]);
            }
#pragma unroll
            for (int nt = 0; nt < 8; nt++) {
                int c = wn * 64 + nt * 8 + g;
                unsigned b[2];
                b[0] = fu(B[c * GP + kb + tg]);
                b[1] = fu(B[c * GP + kb + tg + 4]);
                mma8(acc[0][nt], a[0], b);
                mma8(acc[1][nt], a[1], b);
            }
        }
        __syncthreads();
    }

    int sec = n0 >> 9;
    float* dst = (sec == 0) ? g_Q : (sec == 1 ? g_K : g_V);
    float qs = (sec == 0) ? 0.125f : 1.0f;
#pragma unroll
    for (int mt = 0; mt < 2; mt++) {
#pragma unroll
        for (int half = 0; half < 2; half++) {
            int mm = m0 + wm * 32 + mt * 16 + g + half * 8;
            int bb = mm >> 11, ss = mm & (S_ - 1);
#pragma unroll
            for (int nt = 0; nt < 8; nt++) {
                int col = n0 + wn * 64 + nt * 8 + 2 * tg;
                float2 bi = *(const float2*)(bias + col);
                float v0 = tf32f((acc[mt][nt][half * 2 + 0] + bi.x) * qs);
                float v1 = tf32f((acc[mt][nt][half * 2 + 1] + bi.y) * qs);
                int d = col & (D_ - 1);
                int hh = d >> 6, dh = d & 63;
                float* p = dst + (((size_t)(bb * H_ + hh)) * S_ + ss) * DH_ + dh;
                *(float2*)p = make_float2(v0, v1);
            }
        }
    }
}

// ---------------------------------------------------------------------------
// Flash attention, tf32 mma, cp.async pipelined.
// 128 threads (4 warps x 16 q-rows), 64-key tiles. Separate K (pitch 68,
// conflict-free B-frags) and V (pitch 72) buffers; SP holds Q then P.
// K[t+1] prefetch overlaps softmax+PV; V[t] prefetch overlaps S-compute.
// ---------------------------------------------------------------------------
#define QP 68
#define KP 68
#define VP 72

__global__ __launch_bounds__(128, 4) void attn_kernel() {
    extern __shared__ float sm[];
    float* SP = sm;                  // 64 x 68 : Q, then P
    float* KB = sm + 64 * QP;        // 64 x 68
    float* VB = KB + 64 * KP;        // 64 x 72

    int qt = blockIdx.x, h = blockIdx.y, b = blockIdx.z;
    const float* Qg = g_Q + (((size_t)(b * H_ + h)) * S_ + qt * 64) * DH_;
    const float* Kg = g_K + ((size_t)(b * H_ + h)) * S_ * DH_;
    const float* Vg = g_V + ((size_t)(b * H_ + h)) * S_ * DH_;

    int tid = threadIdx.x, w = tid >> 5, lane = tid & 31;
    int g = lane >> 2, tg = lane & 3;
    int r0 = w * 16;

    // prologue: Q -> SP ; K0 -> KB
#pragma unroll
    for (int p = 0; p < 8; p++) {
        int slot = tid + p * 128, row = slot >> 4, c4 = (slot & 15) * 4;
        CP16(sptr(&SP[row * QP + c4]), Qg + row * DH_ + c4);
    }
    CPCOMMIT;
#pragma unroll
    for (int p = 0; p < 8; p++) {
        int slot = tid + p * 128, row = slot >> 4, c4 = (slot & 15) * 4;
        CP16(sptr(&KB[row * KP + c4]), Kg + row * DH_ + c4);
    }
    CPCOMMIT;
    CPWAIT1;          // Q ready (K0 may be in flight)
    __syncthreads();

    // cache Q A-fragments (8 k-steps)
    unsigned qf[8][4];
#pragma unroll
    for (int ks = 0; ks < 8; ks++) {
        qf[ks][0] = fu(SP[(r0 + g) * QP + ks * 8 + tg]);
        qf[ks][1] = fu(SP[(r0 + g + 8) * QP + ks * 8 + tg]);
        qf[ks][2] = fu(SP[(r0 + g) * QP + ks * 8 + tg + 4]);
        qf[ks][3] = fu(SP[(r0 + g + 8) * QP + ks * 8 + tg + 4]);
    }

    float oacc[8][4];
#pragma unroll
    for (int dt = 0; dt < 8; dt++)
#pragma unroll
        for (int i = 0; i < 4; i++) oacc[dt][i] = 0.f;
    float ml = -CUDART_INF_F, mh = -CUDART_INF_F, ll = 0.f, lh = 0.f;

    for (int kt = 0; kt < NT_; kt++) {
        // issue V[kt]  (VB free: end-of-loop barrier)
        const float* Vt = Vg + (size_t)kt * 64 * DH_;
#pragma unroll
        for (int p = 0; p < 8; p++) {
            int slot = tid + p * 128, row = slot >> 4, c4 = (slot & 15) * 4;
            CP16(sptr(&VB[row * VP + c4]), Vt + row * DH_ + c4);
        }
        CPCOMMIT;
        CPWAIT1;              // K[kt] ready (V[kt] in flight)
        __syncthreads();

        // S = Q K^T
        float s[8][4];
#pragma unroll
        for (int nt = 0; nt < 8; nt++)
#pragma unroll
            for (int i = 0; i < 4; i++) s[nt][i] = 0.f;
#pragma unroll
        for (int ks = 0; ks < 8; ks++) {
            int kb = ks * 8;
#pragma unroll
            for (int nt = 0; nt < 8; nt++) {
                unsigned bb[2];
                bb[0] = fu(KB[(nt * 8 + g) * KP + kb + tg]);
                bb[1] = fu(KB[(nt * 8 + g) * KP + kb + tg + 4]);
                mma8(s[nt], qf[ks], bb);
            }
        }
        __syncthreads();      // KB free

        // prefetch K[kt+1] (wrap on last iter; harmless) — overlaps softmax+PV
        const float* Kt = Kg + (size_t)((kt + 1) & (NT_ - 1)) * 64 * DH_;
#pragma unroll
        for (int p = 0; p < 8; p++) {
            int slot = tid + p * 128, row = slot >> 4, c4 = (slot & 15) * 4;
            CP16(sptr(&KB[row * KP + c4]), Kt + row * DH_ + c4);
        }
        CPCOMMIT;

        // online softmax
        float mxl = -CUDART_INF_F, mxh = -CUDART_INF_F;
#pragma unroll
        for (int nt = 0; nt < 8; nt++) {
            mxl = fmaxf(mxl, fmaxf(s[nt][0], s[nt][1]));
            mxh = fmaxf(mxh, fmaxf(s[nt][2], s[nt][3]));
        }
        mxl = fmaxf(mxl, __shfl_xor_sync(0xffffffffu, mxl, 1));
        mxl = fmaxf(mxl, __shfl_xor_sync(0xffffffffu, mxl, 2));
        mxh = fmaxf(mxh, __shfl_xor_sync(0xffffffffu, mxh, 1));
        mxh = fmaxf(mxh, __shfl_xor_sync(0xffffffffu, mxh, 2));
        float mnl = fmaxf(ml, mxl), mnh = fmaxf(mh, mxh);
        float al = __expf(ml - mnl), ah = __expf(mh - mnh);
        ml = mnl; mh = mnh;
        float rsl = 0.f, rsh = 0.f;
#pragma unroll
        for (int nt = 0; nt < 8; nt++) {
            s[nt][0] = __expf(s[nt][0] - mnl);
            s[nt][1] = __expf(s[nt][1] - mnl);
            s[nt][2] = __expf(s[nt][2] - mnh);
            s[nt][3] = __expf(s[nt][3] - mnh);
            rsl += s[nt][0] + s[nt][1];
            rsh += s[nt][2] + s[nt][3];
        }
        rsl += __shfl_xor_sync(0xffffffffu, rsl, 1);
        rsl += __shfl_xor_sync(0xffffffffu, rsl, 2);
        rsh += __shfl_xor_sync(0xffffffffu, rsh, 1);
        rsh += __shfl_xor_sync(0xffffffffu, rsh, 2);
        ll = ll * al + rsl; lh = lh * ah + rsh;
#pragma unroll
        for (int dt = 0; dt < 8; dt++) {
            oacc[dt][0] *= al; oacc[dt][1] *= al;
            oacc[dt][2] *= ah; oacc[dt][3] *= ah;
        }

        // publish P (own warp's rows)
        int rl = r0 + g, rh = rl + 8;
#pragma unroll
        for (int nt = 0; nt < 8; nt++) {
            int c = nt * 8 + 2 * tg;
            *(float2*)&SP[rl * QP + c] = make_float2(tf32f(s[nt][0]), tf32f(s[nt][1]));
            *(float2*)&SP[rh * QP + c] = make_float2(tf32f(s[nt][2]), tf32f(s[nt][3]));
        }

        CPWAIT1;              // V[kt] ready (K[kt+1] in flight)
        __syncthreads();

        // O += P V
#pragma unroll
        for (int ks = 0; ks < 8; ks++) {
            int kb = ks * 8;
            unsigned pa[4];
            pa[0] = fu(SP[(r0 + g) * QP + kb + tg]);
            pa[1] = fu(SP[(r0 + g + 8) * QP + kb + tg]);
            pa[2] = fu(SP[(r0 + g) * QP + kb + tg + 4]);
            pa[3] = fu(SP[(r0 + g + 8) * QP + kb + tg + 4]);
#pragma unroll
            for (int dt = 0; dt < 8; dt++) {
                unsigned bb[2];
                bb[0] = fu(VB[(kb + tg) * VP + dt * 8 + g]);
                bb[1] = fu(VB[(kb + tg + 4) * VP + dt * 8 + g]);
                mma8(oacc[dt], pa, bb);
            }
        }
        __syncthreads();      // VB free before next V issue
    }

    // epilogue
    float il = 1.0f / ll, ih = 1.0f / lh;
    float* Og = g_O + ((size_t)(b * S_ + qt * 64)) * D_ + h * DH_;
    int rl = r0 + g, rh = rl + 8;
#pragma unroll
    for (int dt = 0; dt < 8; dt++) {
        int c = dt * 8 + 2 * tg;
        *(float2*)&Og[(size_t)rl * D_ + c] =
            make_float2(tf32f(oacc[dt][0] * il), tf32f(oacc[dt][1] * il));
        *(float2*)&Og[(size_t)rh * D_ + c] =
            make_float2(tf32f(oacc[dt][2] * ih), tf32f(oacc[dt][3] * ih));
    }
}

// ---------------------------------------------------------------------------
// Output projection: g_O[16384,512] @ g_Wo^T + b_out -> out (fp32)
// ---------------------------------------------------------------------------
__global__ __launch_bounds__(256, 2) void out_kernel(const float* __restrict__ bias,
                                                     float* __restrict__ out) {
    extern __shared__ float sm[];
    float* As = sm;
    float* Bs = sm + 2*GST;

    int tid = threadIdx.x;
    int m0 = blockIdx.y * 128, n0 = blockIdx.x * 128;
    int w = tid >> 5, lane = tid & 31;
    int wm = w >> 1, wn = w & 1;
    int g = lane >> 2, tg = lane & 3;
    int lr = tid >> 3, lc4 = (tid & 7) * 4;

    const float* X = g_O;
    const float* W = g_Wo;

#define OUT_ISSUE(kc, stg) do {                                               \
        _Pragma("unroll")                                                     \
        for (int p = 0; p < 4; p++) {                                         \
            int row = lr + p * 32;                                            \
            CP16(sptr(&As[(stg)*GST + row*GP + lc4]),                         \
                 X + (size_t)(m0 + row) * D_ + (kc) + lc4);                   \
            CP16(sptr(&Bs[(stg)*GST + row*GP + lc4]),                         \
                 W + (size_t)(n0 + row) * D_ + (kc) + lc4);                   \
        }                                                                     \
        CPCOMMIT;                                                             \
    } while (0)

    OUT_ISSUE(0, 0);

    float acc[2][8][4];
#pragma unroll
    for (int mt = 0; mt < 2; mt++)
#pragma unroll
        for (int nt = 0; nt < 8; nt++)
#pragma unroll
            for (int i = 0; i < 4; i++) acc[mt][nt][i] = 0.f;

    for (int kci = 0; kci < 16; kci++) {
        int cur = kci & 1;
        if (kci + 1 < 16) { OUT_ISSUE((kci + 1) * 32, cur ^ 1); CPWAIT1; }
        else              { CPWAIT0; }
        __syncthreads();
        const float* A = As + cur * GST;
        const float* B = Bs + cur * GST;
#pragma unroll
        for (int ks = 0; ks < 4; ks++) {
            int kb = ks * 8;
            unsigned a[2][4];
#pragma unroll
            for (int mt = 0; mt < 2; mt++) {
                int r = wm * 32 + mt * 16 + g;
                a[mt][0] = fu(A[r * GP + kb + tg]);
                a[mt][1] = fu(A[(r + 8) * GP + kb + tg]);
                a[mt][2] = fu(A[r * GP + kb + tg + 4]);
                a[mt][3] = fu(A[(r + 8) * GP + kb + tg + 4]);
            }
#pragma unroll
            for (int nt = 0; nt < 8; nt++) {
                int c = wn * 64 + nt * 8 + g;
                unsigned b[2];
                b[0] = fu(B[c * GP + kb + tg]);
                b[1] = fu(B[c * GP + kb + tg + 4]);
                mma8(acc[0][nt], a[0], b);
                mma8(acc[1][nt], a[1], b);
            }
        }
        __syncthreads();
    }

#pragma unroll
    for (int mt = 0; mt < 2; mt++) {
#pragma unroll
        for (int half = 0; half < 2; half++) {
            int mm = m0 + wm * 32 + mt * 16 + g + half * 8;
#pragma unroll
            for (int nt = 0; nt < 8; nt++) {
                int col = n0 + wn * 64 + nt * 8 + 2 * tg;
                float2 bi = *(const float2*)(bias + col);
                *(float2*)&out[(size_t)mm * D_ + col] =
                    make_float2(acc[mt][nt][half * 2 + 0] + bi.x,
                                acc[mt][nt][half * 2 + 1] + bi.y);
            }
        }
    }
}

// ---------------------------------------------------------------------------
extern "C" void kernel_launch(void* const* d_in, const int* in_sizes, int n_in,
                              void* d_out, int out_size) {
    const float* x     = (const float*)d_in[0];
    const float* w_in  = (const float*)d_in[1];
    const float* b_in  = (const float*)d_in[2];
    const float* w_out = (const float*)d_in[3];
    const float* b_out = (const float*)d_in[4];
    float* out = (float*)d_out;

    // dynamic smem opt-in (idempotent; stateless; no allocation)
    const int gemm_smem = 4 * GST * 4;                       // 73728 B
    const int attn_smem = (64*QP + 64*KP + 64*VP) * 4;       // 53248 B
    cudaFuncSetAttribute(qkv_kernel,  cudaFuncAttributeMaxDynamicSharedMemorySize, gemm_smem);
    cudaFuncSetAttribute(out_kernel,  cudaFuncAttributeMaxDynamicSharedMemorySize, gemm_smem);
    cudaFuncSetAttribute(attn_kernel, cudaFuncAttributeMaxDynamicSharedMemorySize, attn_smem);

    // tf32 pre-round (keeps cvt.rna accuracy through the cp.async path)
    float* gx;  cudaGetSymbolAddress((void**)&gx,  g_X);
    float* gwi; cudaGetSymbolAddress((void**)&gwi, g_Wi);
    float* gwo; cudaGetSymbolAddress((void**)&gwo, g_Wo);
    round_kernel<<<(M_*D_/4 + 255)/256, 256>>>((const float4*)x,     (float4*)gx,  M_*D_/4);
    round_kernel<<<(3*D_*D_/4 + 255)/256, 256>>>((const float4*)w_in,  (float4*)gwi, 3*D_*D_/4);
    round_kernel<<<(D_*D_/4 + 255)/256, 256>>>((const float4*)w_out, (float4*)gwo, D_*D_/4);

    qkv_kernel<<<dim3(12, 128), 256, gemm_smem>>>(b_in);
    attn_kernel<<<dim3(S_ / 64, H_, B_), 128, attn_smem>>>();
    out_kernel<<<dim3(4, 128), 256, gemm_smem>>>(b_out, out);
}

// round 4
// speedup vs baseline: 4.5139x; 1.1224x over previous
#include <cuda_runtime.h>
#include <math_constants.h>

#define B_  8
#define S_  2048
#define D_  512
#define H_  8
#define DH_ 64
#define M_  (B_*S_)   // 16384
#define NT_ (S_/64)   // 32 key tiles
#define QT_ 128       // q-rows per attention CTA

// Scratch (allocation-free rule: __device__ globals)
__device__ float g_Q[B_*H_*S_*DH_];
__device__ float g_K[B_*H_*S_*DH_];
__device__ float g_V[B_*H_*S_*DH_];
__device__ float g_O[M_*D_];
__device__ float g_X[M_*D_];        // tf32-rounded x
__device__ float g_Wi[3*D_*D_];     // tf32-rounded w_in
__device__ float g_Wo[D_*D_];       // tf32-rounded w_out

// ---------------------------------------------------------------------------
// helpers
// ---------------------------------------------------------------------------
__device__ __forceinline__ unsigned tf32u(float x) {
    unsigned u;
    asm("cvt.rna.tf32.f32 %0, %1;" : "=r"(u) : "f"(x));
    return u;
}
__device__ __forceinline__ float tf32f(float x) { return __uint_as_float(tf32u(x)); }
__device__ __forceinline__ unsigned fu(float x) { return __float_as_uint(x); }

__device__ __forceinline__ void mma8(float* c, const unsigned* a, const unsigned* b) {
    asm volatile(
        "mma.sync.aligned.m16n8k8.row.col.f32.tf32.tf32.f32 "
        "{%0,%1,%2,%3}, {%4,%5,%6,%7}, {%8,%9}, {%0,%1,%2,%3};"
        : "+f"(c[0]), "+f"(c[1]), "+f"(c[2]), "+f"(c[3])
        : "r"(a[0]), "r"(a[1]), "r"(a[2]), "r"(a[3]), "r"(b[0]), "r"(b[1]));
}

__device__ __forceinline__ unsigned sptr(const void* p) {
    return (unsigned)__cvta_generic_to_shared(p);
}
#define CP16(d, s)  asm volatile("cp.async.cg.shared.global [%0], [%1], 16;\n" :: "r"(d), "l"(s))
#define CPCOMMIT    asm volatile("cp.async.commit_group;\n")
#define CPWAIT1     asm volatile("cp.async.wait_group 1;\n")
#define CPWAIT0     asm volatile("cp.async.wait_group 0;\n")

// ---------------------------------------------------------------------------
// tf32 pre-round (elementwise, float4)
// ---------------------------------------------------------------------------
__global__ void round_kernel(const float4* __restrict__ in, float4* __restrict__ out, int n4) {
    int i = blockIdx.x * 256 + threadIdx.x;
    if (i < n4) {
        float4 v = in[i];
        out[i] = make_float4(tf32f(v.x), tf32f(v.y), tf32f(v.z), tf32f(v.w));
    }
}

// ---------------------------------------------------------------------------
// QKV projection: g_X[16384,512] @ g_Wi^T + b -> scatter tf32-rounded to Q,K,V
// 128x128 tile, 256 threads, k-chunk 32, 2-stage cp.async pipeline. pitch 36.
// ---------------------------------------------------------------------------
#define GP 36
#define GST (128*GP)   // 4608 floats per stage

__global__ __launch_bounds__(256, 2) void qkv_kernel(const float* __restrict__ bias) {
    extern __shared__ float sm[];
    float* As = sm;              // 2 stages
    float* Bs = sm + 2*GST;

    int tid = threadIdx.x;
    int m0 = blockIdx.y * 128, n0 = blockIdx.x * 128;
    int w = tid >> 5, lane = tid & 31;
    int wm = w >> 1, wn = w & 1;
    int g = lane >> 2, tg = lane & 3;
    int lr = tid >> 3, lc4 = (tid & 7) * 4;

    const float* X = g_X;
    const float* W = g_Wi;

#define QKV_ISSUE(kc, stg) do {                                               \
        _Pragma("unroll")                                                     \
        for (int p = 0; p < 4; p++) {                                         \
            int row = lr + p * 32;                                            \
            CP16(sptr(&As[(stg)*GST + row*GP + lc4]),                         \
                 X + (size_t)(m0 + row) * D_ + (kc) + lc4);                   \
            CP16(sptr(&Bs[(stg)*GST + row*GP + lc4]),                         \
                 W + (size_t)(n0 + row) * D_ + (kc) + lc4);                   \
        }                                                                     \
        CPCOMMIT;                                                             \
    } while (0)

    QKV_ISSUE(0, 0);

    float acc[2][8][4];
#pragma unroll
    for (int mt = 0; mt < 2; mt++)
#pragma unroll
        for (int nt = 0; nt < 8; nt++)
#pragma unroll
            for (int i = 0; i < 4; i++) acc[mt][nt][i] = 0.f;

    for (int kci = 0; kci < 16; kci++) {
        int cur = kci & 1;
        if (kci + 1 < 16) { QKV_ISSUE((kci + 1) * 32, cur ^ 1); CPWAIT1; }
        else              { CPWAIT0; }
        __syncthreads();
        const float* A = As + cur * GST;
        const float* B = Bs + cur * GST;
#pragma unroll
        for (int ks = 0; ks < 4; ks++) {
            int kb = ks * 8;
            unsigned a[2][4];
#pragma unroll
            for (int mt = 0; mt < 2; mt++) {
                int r = wm * 32 + mt * 16 + g;
                a[mt][0] = fu(A[r * GP + kb + tg]);
                a[mt][1] = fu(A[(r + 8) * GP + kb + tg]);
                a[mt][2] = fu(A[r * GP + kb + tg + 4]);
                a[mt][3] = fu(A[(r + 8) * GP + kb + tg + 4]);
            }
#pragma unroll
            for (int nt = 0; nt < 8; nt++) {
                int c = wn * 64 + nt * 8 + g;
                unsigned b[2];
                b[0] = fu(B[c * GP + kb + tg]);
                b[1] = fu(B[c * GP + kb + tg + 4]);
                mma8(acc[0][nt], a[0], b);
                mma8(acc[1][nt], a[1], b);
            }
        }
        __syncthreads();
    }

    int sec = n0 >> 9;
    float* dst = (sec == 0) ? g_Q : (sec == 1 ? g_K : g_V);
    float qs = (sec == 0) ? 0.125f : 1.0f;
#pragma unroll
    for (int mt = 0; mt < 2; mt++) {
#pragma unroll
        for (int half = 0; half < 2; half++) {
            int mm = m0 + wm * 32 + mt * 16 + g + half * 8;
            int bb = mm >> 11, ss = mm & (S_ - 1);
#pragma unroll
            for (int nt = 0; nt < 8; nt++) {
                int col = n0 + wn * 64 + nt * 8 + 2 * tg;
                float2 bi = *(const float2*)(bias + col);
                float v0 = tf32f((acc[mt][nt][half * 2 + 0] + bi.x) * qs);
                float v1 = tf32f((acc[mt][nt][half * 2 + 1] + bi.y) * qs);
                int d = col & (D_ - 1);
                int hh = d >> 6, dh = d & 63;
                float* p = dst + (((size_t)(bb * H_ + hh)) * S_ + ss) * DH_ + dh;
                *(float2*)p = make_float2(v0, v1);
            }
        }
    }
}

// ---------------------------------------------------------------------------
// Flash attention, tf32 mma, cp.async pipelined.
// CTA = 128 q-rows, 128 threads (4 warps x 32 q-rows = 2 m-frags each).
// K/V B-fragments amortized over 2 m-frags (LDS/mma 2.5 -> 1.37).
// K pitch 68 (conflict-free), V pitch 72 (conflict-free), SP holds Q then P.
// ---------------------------------------------------------------------------
#define QP 68
#define KP 68
#define VP 72

__global__ __launch_bounds__(128, 2) void attn_kernel() {
    extern __shared__ float sm[];
    float* SP = sm;                  // 128 x 68 : Q, then P
    float* KB = sm + QT_ * QP;       // 64 x 68
    float* VB = KB + 64 * KP;        // 64 x 72

    int qt = blockIdx.x, h = blockIdx.y, b = blockIdx.z;
    const float* Qg = g_Q + (((size_t)(b * H_ + h)) * S_ + qt * QT_) * DH_;
    const float* Kg = g_K + ((size_t)(b * H_ + h)) * S_ * DH_;
    const float* Vg = g_V + ((size_t)(b * H_ + h)) * S_ * DH_;

    int tid = threadIdx.x, w = tid >> 5, lane = tid & 31;
    int g = lane >> 2, tg = lane & 3;
    int r0 = w * 32;                 // warp owns rows [r0, r0+32)

    // prologue: Q(128x64) -> SP ; K0 -> KB
#pragma unroll
    for (int p = 0; p < 16; p++) {
        int slot = tid + p * 128, row = slot >> 4, c4 = (slot & 15) * 4;
        CP16(sptr(&SP[row * QP + c4]), Qg + row * DH_ + c4);
    }
    CPCOMMIT;
#pragma unroll
    for (int p = 0; p < 8; p++) {
        int slot = tid + p * 128, row = slot >> 4, c4 = (slot & 15) * 4;
        CP16(sptr(&KB[row * KP + c4]), Kg + row * DH_ + c4);
    }
    CPCOMMIT;
    CPWAIT1;          // Q ready (K0 in flight)
    __syncthreads();

    // cache Q A-fragments: 2 m-frags x 8 k-steps
    unsigned qf[2][8][4];
#pragma unroll
    for (int f = 0; f < 2; f++) {
        int rl = r0 + f * 16 + g;
#pragma unroll
        for (int ks = 0; ks < 8; ks++) {
            qf[f][ks][0] = fu(SP[rl * QP + ks * 8 + tg]);
            qf[f][ks][1] = fu(SP[(rl + 8) * QP + ks * 8 + tg]);
            qf[f][ks][2] = fu(SP[rl * QP + ks * 8 + tg + 4]);
            qf[f][ks][3] = fu(SP[(rl + 8) * QP + ks * 8 + tg + 4]);
        }
    }

    float oacc[2][8][4];
#pragma unroll
    for (int f = 0; f < 2; f++)
#pragma unroll
        for (int dt = 0; dt < 8; dt++)
#pragma unroll
            for (int i = 0; i < 4; i++) oacc[f][dt][i] = 0.f;
    float mrow[2][2], lrow[2][2];
#pragma unroll
    for (int f = 0; f < 2; f++) {
        mrow[f][0] = -CUDART_INF_F; mrow[f][1] = -CUDART_INF_F;
        lrow[f][0] = 0.f; lrow[f][1] = 0.f;
    }

    for (int kt = 0; kt < NT_; kt++) {
        // issue V[kt]
        const float* Vt = Vg + (size_t)kt * 64 * DH_;
#pragma unroll
        for (int p = 0; p < 8; p++) {
            int slot = tid + p * 128, row = slot >> 4, c4 = (slot & 15) * 4;
            CP16(sptr(&VB[row * VP + c4]), Vt + row * DH_ + c4);
        }
        CPCOMMIT;
        CPWAIT1;              // K[kt] ready (V[kt] in flight)
        __syncthreads();

        // S = Q K^T for both m-frags, shared B-frags
        float s[2][8][4];
#pragma unroll
        for (int f = 0; f < 2; f++)
#pragma unroll
            for (int nt = 0; nt < 8; nt++)
#pragma unroll
                for (int i = 0; i < 4; i++) s[f][nt][i] = 0.f;
#pragma unroll
        for (int ks = 0; ks < 8; ks++) {
            int kb = ks * 8;
#pragma unroll
            for (int nt = 0; nt < 8; nt++) {
                unsigned bb[2];
                bb[0] = fu(KB[(nt * 8 + g) * KP + kb + tg]);
                bb[1] = fu(KB[(nt * 8 + g) * KP + kb + tg + 4]);
                mma8(s[0][nt], qf[0][ks], bb);
                mma8(s[1][nt], qf[1][ks], bb);
            }
        }
        __syncthreads();      // KB free

        // prefetch K[kt+1] — overlaps softmax + PV
        const float* Kt = Kg + (size_t)((kt + 1) & (NT_ - 1)) * 64 * DH_;
#pragma unroll
        for (int p = 0; p < 8; p++) {
            int slot = tid + p * 128, row = slot >> 4, c4 = (slot & 15) * 4;
            CP16(sptr(&KB[row * KP + c4]), Kt + row * DH_ + c4);
        }
        CPCOMMIT;

        // online softmax, per m-frag
#pragma unroll
        for (int f = 0; f < 2; f++) {
            float mxl = -CUDART_INF_F, mxh = -CUDART_INF_F;
#pragma unroll
            for (int nt = 0; nt < 8; nt++) {
                mxl = fmaxf(mxl, fmaxf(s[f][nt][0], s[f][nt][1]));
                mxh = fmaxf(mxh, fmaxf(s[f][nt][2], s[f][nt][3]));
            }
            mxl = fmaxf(mxl, __shfl_xor_sync(0xffffffffu, mxl, 1));
            mxl = fmaxf(mxl, __shfl_xor_sync(0xffffffffu, mxl, 2));
            mxh = fmaxf(mxh, __shfl_xor_sync(0xffffffffu, mxh, 1));
            mxh = fmaxf(mxh, __shfl_xor_sync(0xffffffffu, mxh, 2));
            float mnl = fmaxf(mrow[f][0], mxl), mnh = fmaxf(mrow[f][1], mxh);
            float al = __expf(mrow[f][0] - mnl), ah = __expf(mrow[f][1] - mnh);
            mrow[f][0] = mnl; mrow[f][1] = mnh;
            float rsl = 0.f, rsh = 0.f;
#pragma unroll
            for (int nt = 0; nt < 8; nt++) {
                s[f][nt][0] = __expf(s[f][nt][0] - mnl);
                s[f][nt][1] = __expf(s[f][nt][1] - mnl);
                s[f][nt][2] = __expf(s[f][nt][2] - mnh);
                s[f][nt][3] = __expf(s[f][nt][3] - mnh);
                rsl += s[f][nt][0] + s[f][nt][1];
                rsh += s[f][nt][2] + s[f][nt][3];
            }
            rsl += __shfl_xor_sync(0xffffffffu, rsl, 1);
            rsl += __shfl_xor_sync(0xffffffffu, rsl, 2);
            rsh += __shfl_xor_sync(0xffffffffu, rsh, 1);
            rsh += __shfl_xor_sync(0xffffffffu, rsh, 2);
            lrow[f][0] = lrow[f][0] * al + rsl;
            lrow[f][1] = lrow[f][1] * ah + rsh;
#pragma unroll
            for (int dt = 0; dt < 8; dt++) {
                oacc[f][dt][0] *= al; oacc[f][dt][1] *= al;
                oacc[f][dt][2] *= ah; oacc[f][dt][3] *= ah;
            }
            // publish P rows for this frag
            int rl = r0 + f * 16 + g, rh = rl + 8;
#pragma unroll
            for (int nt = 0; nt < 8; nt++) {
                int c = nt * 8 + 2 * tg;
                *(float2*)&SP[rl * QP + c] = make_float2(tf32f(s[f][nt][0]), tf32f(s[f][nt][1]));
                *(float2*)&SP[rh * QP + c] = make_float2(tf32f(s[f][nt][2]), tf32f(s[f][nt][3]));
            }
        }

        CPWAIT1;              // V[kt] ready (K[kt+1] in flight)
        __syncthreads();

        // O += P V, shared V B-frags across both m-frags
#pragma unroll
        for (int ks = 0; ks < 8; ks++) {
            int kb = ks * 8;
            unsigned pa[2][4];
#pragma unroll
            for (int f = 0; f < 2; f++) {
                int rl = r0 + f * 16 + g;
                pa[f][0] = fu(SP[rl * QP + kb + tg]);
                pa[f][1] = fu(SP[(rl + 8) * QP + kb + tg]);
                pa[f][2] = fu(SP[rl * QP + kb + tg + 4]);
                pa[f][3] = fu(SP[(rl + 8) * QP + kb + tg + 4]);
            }
#pragma unroll
            for (int dt = 0; dt < 8; dt++) {
                unsigned bb[2];
                bb[0] = fu(VB[(kb + tg) * VP + dt * 8 + g]);
                bb[1] = fu(VB[(kb + tg + 4) * VP + dt * 8 + g]);
                mma8(oacc[0][dt], pa[0], bb);
                mma8(oacc[1][dt], pa[1], bb);
            }
        }
        __syncthreads();      // VB free before next V issue
    }

    // epilogue
    float* Og = g_O + ((size_t)(b * S_ + qt * QT_)) * D_ + h * DH_;
#pragma unroll
    for (int f = 0; f < 2; f++) {
        float il = 1.0f / lrow[f][0], ih = 1.0f / lrow[f][1];
        int rl = r0 + f * 16 + g, rh = rl + 8;
#pragma unroll
        for (int dt = 0; dt < 8; dt++) {
            int c = dt * 8 + 2 * tg;
            *(float2*)&Og[(size_t)rl * D_ + c] =
                make_float2(tf32f(oacc[f][dt][0] * il), tf32f(oacc[f][dt][1] * il));
            *(float2*)&Og[(size_t)rh * D_ + c] =
                make_float2(tf32f(oacc[f][dt][2] * ih), tf32f(oacc[f][dt][3] * ih));
        }
    }
}

// ---------------------------------------------------------------------------
// Output projection: g_O[16384,512] @ g_Wo^T + b_out -> out (fp32)
// ---------------------------------------------------------------------------
__global__ __launch_bounds__(256, 2) void out_kernel(const float* __restrict__ bias,
                                                     float* __restrict__ out) {
    extern __shared__ float sm[];
    float* As = sm;
    float* Bs = sm + 2*GST;

    int tid = threadIdx.x;
    int m0 = blockIdx.y * 128, n0 = blockIdx.x * 128;
    int w = tid >> 5, lane = tid & 31;
    int wm = w >> 1, wn = w & 1;
    int g = lane >> 2, tg = lane & 3;
    int lr = tid >> 3, lc4 = (tid & 7) * 4;

    const float* X = g_O;
    const float* W = g_Wo;

#define OUT_ISSUE(kc, stg) do {                                               \
        _Pragma("unroll")                                                     \
        for (int p = 0; p < 4; p++) {                                         \
            int row = lr + p * 32;                                            \
            CP16(sptr(&As[(stg)*GST + row*GP + lc4]),                         \
                 X + (size_t)(m0 + row) * D_ + (kc) + lc4);                   \
            CP16(sptr(&Bs[(stg)*GST + row*GP + lc4]),                         \
                 W + (size_t)(n0 + row) * D_ + (kc) + lc4);                   \
        }                                                                     \
        CPCOMMIT;                                                             \
    } while (0)

    OUT_ISSUE(0, 0);

    float acc[2][8][4];
#pragma unroll
    for (int mt = 0; mt < 2; mt++)
#pragma unroll
        for (int nt = 0; nt < 8; nt++)
#pragma unroll
            for (int i = 0; i < 4; i++) acc[mt][nt][i] = 0.f;

    for (int kci = 0; kci < 16; kci++) {
        int cur = kci & 1;
        if (kci + 1 < 16) { OUT_ISSUE((kci + 1) * 32, cur ^ 1); CPWAIT1; }
        else              { CPWAIT0; }
        __syncthreads();
        const float* A = As + cur * GST;
        const float* B = Bs + cur * GST;
#pragma unroll
        for (int ks = 0; ks < 4; ks++) {
            int kb = ks * 8;
            unsigned a[2][4];
#pragma unroll
            for (int mt = 0; mt < 2; mt++) {
                int r = wm * 32 + mt * 16 + g;
                a[mt][0] = fu(A[r * GP + kb + tg]);
                a[mt][1] = fu(A[(r + 8) * GP + kb + tg]);
                a[mt][2] = fu(A[r * GP + kb + tg + 4]);
                a[mt][3] = fu(A[(r + 8) * GP + kb + tg + 4]);
            }
#pragma unroll
            for (int nt = 0; nt < 8; nt++) {
                int c = wn * 64 + nt * 8 + g;
                unsigned b[2];
                b[0] = fu(B[c * GP + kb + tg]);
                b[1] = fu(B[c * GP + kb + tg + 4]);
                mma8(acc[0][nt], a[0], b);
                mma8(acc[1][nt], a[1], b);
            }
        }
        __syncthreads();
    }

#pragma unroll
    for (int mt = 0; mt < 2; mt++) {
#pragma unroll
        for (int half = 0; half < 2; half++) {
            int mm = m0 + wm * 32 + mt * 16 + g + half * 8;
#pragma unroll
            for (int nt = 0; nt < 8; nt++) {
                int col = n0 + wn * 64 + nt * 8 + 2 * tg;
                float2 bi = *(const float2*)(bias + col);
                *(float2*)&out[(size_t)mm * D_ + col] =
                    make_float2(acc[mt][nt][half * 2 + 0] + bi.x,
                                acc[mt][nt][half * 2 + 1] + bi.y);
            }
        }
    }
}

// ---------------------------------------------------------------------------
extern "C" void kernel_launch(void* const* d_in, const int* in_sizes, int n_in,
                              void* d_out, int out_size) {
    const float* x     = (const float*)d_in[0];
    const float* w_in  = (const float*)d_in[1];
    const float* b_in  = (const float*)d_in[2];
    const float* w_out = (const float*)d_in[3];
    const float* b_out = (const float*)d_in[4];
    float* out = (float*)d_out;

    const int gemm_smem = 4 * GST * 4;                          // 73728 B
    const int attn_smem = (QT_*QP + 64*KP + 64*VP) * 4;         // 70656 B
    cudaFuncSetAttribute(qkv_kernel,  cudaFuncAttributeMaxDynamicSharedMemorySize, gemm_smem);
    cudaFuncSetAttribute(out_kernel,  cudaFuncAttributeMaxDynamicSharedMemorySize, gemm_smem);
    cudaFuncSetAttribute(attn_kernel, cudaFuncAttributeMaxDynamicSharedMemorySize, attn_smem);

    float* gx;  cudaGetSymbolAddress((void**)&gx,  g_X);
    float* gwi; cudaGetSymbolAddress((void**)&gwi, g_Wi);
    float* gwo; cudaGetSymbolAddress((void**)&gwo, g_Wo);
    round_kernel<<<(M_*D_/4 + 255)/256, 256>>>((const float4*)x,     (float4*)gx,  M_*D_/4);
    round_kernel<<<(3*D_*D_/4 + 255)/256, 256>>>((const float4*)w_in,  (float4*)gwi, 3*D_*D_/4);
    round_kernel<<<(D_*D_/4 + 255)/256, 256>>>((const float4*)w_out, (float4*)gwo, D_*D_/4);

    qkv_kernel<<<dim3(12, 128), 256, gemm_smem>>>(b_in);
    attn_kernel<<<dim3(S_ / QT_, H_, B_), 128, attn_smem>>>();
    out_kernel<<<dim3(4, 128), 256, gemm_smem>>>(b_out, out);
}

// round 5
// speedup vs baseline: 4.7897x; 1.0611x over previous
#include <cuda_runtime.h>
#include <math_constants.h>

#define B_  8
#define S_  2048
#define D_  512
#define H_  8
#define DH_ 64
#define M_  (B_*S_)   // 16384
#define NT_ (S_/64)   // 32 key tiles
#define QT_ 128       // q-rows per attention CTA

// Scratch (allocation-free rule: __device__ globals)
__device__ float g_Q[B_*H_*S_*DH_];
__device__ float g_K[B_*H_*S_*DH_];
__device__ float g_V[B_*H_*S_*DH_];
__device__ float g_O[M_*D_];
__device__ float g_X[M_*D_];        // tf32-rounded x
__device__ float g_Wi[3*D_*D_];     // tf32-rounded w_in
__device__ float g_Wo[D_*D_];       // tf32-rounded w_out

// ---------------------------------------------------------------------------
// helpers
// ---------------------------------------------------------------------------
__device__ __forceinline__ unsigned tf32u(float x) {
    unsigned u;
    asm("cvt.rna.tf32.f32 %0, %1;" : "=r"(u) : "f"(x));
    return u;
}
__device__ __forceinline__ float tf32f(float x) { return __uint_as_float(tf32u(x)); }
__device__ __forceinline__ unsigned fu(float x) { return __float_as_uint(x); }

__device__ __forceinline__ void mma8(float* c, const unsigned* a, const unsigned* b) {
    asm volatile(
        "mma.sync.aligned.m16n8k8.row.col.f32.tf32.tf32.f32 "
        "{%0,%1,%2,%3}, {%4,%5,%6,%7}, {%8,%9}, {%0,%1,%2,%3};"
        : "+f"(c[0]), "+f"(c[1]), "+f"(c[2]), "+f"(c[3])
        : "r"(a[0]), "r"(a[1]), "r"(a[2]), "r"(a[3]), "r"(b[0]), "r"(b[1]));
}

// 4-matrix ldmatrix: for tf32, each m8n8.b16 matrix = 8 rows x 4 tf32 cols.
__device__ __forceinline__ void ldsm4(unsigned* r, unsigned addr) {
    asm volatile("ldmatrix.sync.aligned.m8n8.x4.shared.b16 {%0,%1,%2,%3}, [%4];"
                 : "=r"(r[0]), "=r"(r[1]), "=r"(r[2]), "=r"(r[3]) : "r"(addr));
}

__device__ __forceinline__ unsigned sptr(const void* p) {
    return (unsigned)__cvta_generic_to_shared(p);
}
#define CP16(d, s)  asm volatile("cp.async.cg.shared.global [%0], [%1], 16;\n" :: "r"(d), "l"(s))
#define CPCOMMIT    asm volatile("cp.async.commit_group;\n")
#define CPWAIT1     asm volatile("cp.async.wait_group 1;\n")
#define CPWAIT0     asm volatile("cp.async.wait_group 0;\n")

// ---------------------------------------------------------------------------
// tf32 pre-round (elementwise, float4)
// ---------------------------------------------------------------------------
__global__ void round_kernel(const float4* __restrict__ in, float4* __restrict__ out, int n4) {
    int i = blockIdx.x * 256 + threadIdx.x;
    if (i < n4) {
        float4 v = in[i];
        out[i] = make_float4(tf32f(v.x), tf32f(v.y), tf32f(v.z), tf32f(v.w));
    }
}

// ---------------------------------------------------------------------------
// QKV projection: g_X[16384,512] @ g_Wi^T + b -> scatter tf32-rounded to Q,K,V
// 128x128 tile, 256 threads, k-chunk 32, 2-stage cp.async, LDSM fragments.
// ---------------------------------------------------------------------------
#define GP 36
#define GST (128*GP)   // 4608 floats per stage

__global__ __launch_bounds__(256, 2) void qkv_kernel(const float* __restrict__ bias) {
    extern __shared__ float sm[];
    float* As = sm;              // 2 stages
    float* Bs = sm + 2*GST;

    int tid = threadIdx.x;
    int m0 = blockIdx.y * 128, n0 = blockIdx.x * 128;
    int w = tid >> 5, lane = tid & 31;
    int wm = w >> 1, wn = w & 1;
    int g = lane >> 2, tg = lane & 3;
    int lr = tid >> 3, lc4 = (tid & 7) * 4;
    int l8 = lane & 7, b3 = (lane >> 3) & 1, b4 = lane >> 4;

    const float* X = g_X;
    const float* W = g_Wi;

    // LDSM base byte-addresses (stage 0, kb 0)
    unsigned aA[2], aB[4];
#pragma unroll
    for (int mt = 0; mt < 2; mt++)
        aA[mt] = sptr(As) + ((wm*32 + mt*16 + l8 + b3*8) * GP + b4*4) * 4;
#pragma unroll
    for (int p = 0; p < 4; p++)
        aB[p] = sptr(Bs) + ((wn*64 + (2*p + b4)*8 + l8) * GP + b3*4) * 4;

#define QKV_ISSUE(kc, stg) do {                                               \
        _Pragma("unroll")                                                     \
        for (int p = 0; p < 4; p++) {                                         \
            int row = lr + p * 32;                                            \
            CP16(sptr(&As[(stg)*GST + row*GP + lc4]),                         \
                 X + (size_t)(m0 + row) * D_ + (kc) + lc4);                   \
            CP16(sptr(&Bs[(stg)*GST + row*GP + lc4]),                         \
                 W + (size_t)(n0 + row) * D_ + (kc) + lc4);                   \
        }                                                                     \
        CPCOMMIT;                                                             \
    } while (0)

    QKV_ISSUE(0, 0);

    float acc[2][8][4];
#pragma unroll
    for (int mt = 0; mt < 2; mt++)
#pragma unroll
        for (int nt = 0; nt < 8; nt++)
#pragma unroll
            for (int i = 0; i < 4; i++) acc[mt][nt][i] = 0.f;

    for (int kci = 0; kci < 16; kci++) {
        int cur = kci & 1;
        if (kci + 1 < 16) { QKV_ISSUE((kci + 1) * 32, cur ^ 1); CPWAIT1; }
        else              { CPWAIT0; }
        __syncthreads();
        unsigned sb = cur * (GST * 4);
#pragma unroll
        for (int ks = 0; ks < 4; ks++) {
            unsigned kbb = sb + ks * 32;
            unsigned a0[4], a1[4];
            ldsm4(a0, aA[0] + kbb);
            ldsm4(a1, aA[1] + kbb);
#pragma unroll
            for (int p = 0; p < 4; p++) {
                unsigned bb[4];
                ldsm4(bb, aB[p] + kbb);
                mma8(acc[0][2*p],   a0, bb);
                mma8(acc[1][2*p],   a1, bb);
                mma8(acc[0][2*p+1], a0, bb + 2);
                mma8(acc[1][2*p+1], a1, bb + 2);
            }
        }
        __syncthreads();
    }

    int sec = n0 >> 9;
    float* dst = (sec == 0) ? g_Q : (sec == 1 ? g_K : g_V);
    float qs = (sec == 0) ? 0.125f : 1.0f;
#pragma unroll
    for (int mt = 0; mt < 2; mt++) {
#pragma unroll
        for (int half = 0; half < 2; half++) {
            int mm = m0 + wm * 32 + mt * 16 + g + half * 8;
            int bb = mm >> 11, ss = mm & (S_ - 1);
#pragma unroll
            for (int nt = 0; nt < 8; nt++) {
                int col = n0 + wn * 64 + nt * 8 + 2 * tg;
                float2 bi = *(const float2*)(bias + col);
                float v0 = tf32f((acc[mt][nt][half * 2 + 0] + bi.x) * qs);
                float v1 = tf32f((acc[mt][nt][half * 2 + 1] + bi.y) * qs);
                int d = col & (D_ - 1);
                int hh = d >> 6, dh = d & 63;
                float* p = dst + (((size_t)(bb * H_ + hh)) * S_ + ss) * DH_ + dh;
                *(float2*)p = make_float2(v0, v1);
            }
        }
    }
}

// ---------------------------------------------------------------------------
// Flash attention, tf32 mma, cp.async pipelined, LDSM fragments (Q, K, P).
// CTA = 128 q-rows, 128 threads (4 warps x 32 q-rows = 2 m-frags each).
// ---------------------------------------------------------------------------
#define QP 68
#define KP 68
#define VP 72

__global__ __launch_bounds__(128, 2) void attn_kernel() {
    extern __shared__ float sm[];
    float* SP = sm;                  // 128 x 68 : Q, then P
    float* KB = sm + QT_ * QP;       // 64 x 68
    float* VB = KB + 64 * KP;        // 64 x 72

    int qt = blockIdx.x, h = blockIdx.y, b = blockIdx.z;
    const float* Qg = g_Q + (((size_t)(b * H_ + h)) * S_ + qt * QT_) * DH_;
    const float* Kg = g_K + ((size_t)(b * H_ + h)) * S_ * DH_;
    const float* Vg = g_V + ((size_t)(b * H_ + h)) * S_ * DH_;

    int tid = threadIdx.x, w = tid >> 5, lane = tid & 31;
    int g = lane >> 2, tg = lane & 3;
    int l8 = lane & 7, b3 = (lane >> 3) & 1, b4 = lane >> 4;
    int r0 = w * 32;                 // warp owns rows [r0, r0+32)

    // LDSM base addresses
    unsigned aSP[2], aK[4];
#pragma unroll
    for (int f = 0; f < 2; f++)
        aSP[f] = sptr(SP) + ((r0 + f*16 + l8 + b3*8) * QP + b4*4) * 4;
#pragma unroll
    for (int p = 0; p < 4; p++)
        aK[p] = sptr(KB) + (((2*p + b4)*8 + l8) * KP + b3*4) * 4;

    // prologue: Q(128x64) -> SP ; K0 -> KB
#pragma unroll
    for (int p = 0; p < 16; p++) {
        int slot = tid + p * 128, row = slot >> 4, c4 = (slot & 15) * 4;
        CP16(sptr(&SP[row * QP + c4]), Qg + row * DH_ + c4);
    }
    CPCOMMIT;
#pragma unroll
    for (int p = 0; p < 8; p++) {
        int slot = tid + p * 128, row = slot >> 4, c4 = (slot & 15) * 4;
        CP16(sptr(&KB[row * KP + c4]), Kg + row * DH_ + c4);
    }
    CPCOMMIT;
    CPWAIT1;          // Q ready (K0 in flight)
    __syncthreads();

    // cache Q A-fragments: 2 m-frags x 8 k-steps (LDSM)
    unsigned qf[2][8][4];
#pragma unroll
    for (int f = 0; f < 2; f++)
#pragma unroll
        for (int ks = 0; ks < 8; ks++)
            ldsm4(qf[f][ks], aSP[f] + ks * 32);

    float oacc[2][8][4];
#pragma unroll
    for (int f = 0; f < 2; f++)
#pragma unroll
        for (int dt = 0; dt < 8; dt++)
#pragma unroll
            for (int i = 0; i < 4; i++) oacc[f][dt][i] = 0.f;
    float mrow[2][2], lrow[2][2];
#pragma unroll
    for (int f = 0; f < 2; f++) {
        mrow[f][0] = -CUDART_INF_F; mrow[f][1] = -CUDART_INF_F;
        lrow[f][0] = 0.f; lrow[f][1] = 0.f;
    }

    for (int kt = 0; kt < NT_; kt++) {
        // issue V[kt]
        const float* Vt = Vg + (size_t)kt * 64 * DH_;
#pragma unroll
        for (int p = 0; p < 8; p++) {
            int slot = tid + p * 128, row = slot >> 4, c4 = (slot & 15) * 4;
            CP16(sptr(&VB[row * VP + c4]), Vt + row * DH_ + c4);
        }
        CPCOMMIT;
        CPWAIT1;              // K[kt] ready (V[kt] in flight)
        __syncthreads();

        // S = Q K^T for both m-frags, LDSM B-frags (2 n-tiles per LDSM)
        float s[2][8][4];
#pragma unroll
        for (int f = 0; f < 2; f++)
#pragma unroll
            for (int nt = 0; nt < 8; nt++)
#pragma unroll
                for (int i = 0; i < 4; i++) s[f][nt][i] = 0.f;
#pragma unroll
        for (int ks = 0; ks < 8; ks++) {
            unsigned kbb = ks * 32;
#pragma unroll
            for (int p = 0; p < 4; p++) {
                unsigned bb[4];
                ldsm4(bb, aK[p] + kbb);
                mma8(s[0][2*p],   qf[0][ks], bb);
                mma8(s[1][2*p],   qf[1][ks], bb);
                mma8(s[0][2*p+1], qf[0][ks], bb + 2);
                mma8(s[1][2*p+1], qf[1][ks], bb + 2);
            }
        }
        __syncthreads();      // KB free

        // prefetch K[kt+1] — overlaps softmax + PV
        const float* Kt = Kg + (size_t)((kt + 1) & (NT_ - 1)) * 64 * DH_;
#pragma unroll
        for (int p = 0; p < 8; p++) {
            int slot = tid + p * 128, row = slot >> 4, c4 = (slot & 15) * 4;
            CP16(sptr(&KB[row * KP + c4]), Kt + row * DH_ + c4);
        }
        CPCOMMIT;

        // online softmax, per m-frag
#pragma unroll
        for (int f = 0; f < 2; f++) {
            float mxl = -CUDART_INF_F, mxh = -CUDART_INF_F;
#pragma unroll
            for (int nt = 0; nt < 8; nt++) {
                mxl = fmaxf(mxl, fmaxf(s[f][nt][0], s[f][nt][1]));
                mxh = fmaxf(mxh, fmaxf(s[f][nt][2], s[f][nt][3]));
            }
            mxl = fmaxf(mxl, __shfl_xor_sync(0xffffffffu, mxl, 1));
            mxl = fmaxf(mxl, __shfl_xor_sync(0xffffffffu, mxl, 2));
            mxh = fmaxf(mxh, __shfl_xor_sync(0xffffffffu, mxh, 1));
            mxh = fmaxf(mxh, __shfl_xor_sync(0xffffffffu, mxh, 2));
            float mnl = fmaxf(mrow[f][0], mxl), mnh = fmaxf(mrow[f][1], mxh);
            float al = __expf(mrow[f][0] - mnl), ah = __expf(mrow[f][1] - mnh);
            mrow[f][0] = mnl; mrow[f][1] = mnh;
            float rsl = 0.f, rsh = 0.f;
#pragma unroll
            for (int nt = 0; nt < 8; nt++) {
                s[f][nt][0] = __expf(s[f][nt][0] - mnl);
                s[f][nt][1] = __expf(s[f][nt][1] - mnl);
                s[f][nt][2] = __expf(s[f][nt][2] - mnh);
                s[f][nt][3] = __expf(s[f][nt][3] - mnh);
                rsl += s[f][nt][0] + s[f][nt][1];
                rsh += s[f][nt][2] + s[f][nt][3];
            }
            rsl += __shfl_xor_sync(0xffffffffu, rsl, 1);
            rsl += __shfl_xor_sync(0xffffffffu, rsl, 2);
            rsh += __shfl_xor_sync(0xffffffffu, rsh, 1);
            rsh += __shfl_xor_sync(0xffffffffu, rsh, 2);
            lrow[f][0] = lrow[f][0] * al + rsl;
            lrow[f][1] = lrow[f][1] * ah + rsh;
#pragma unroll
            for (int dt = 0; dt < 8; dt++) {
                oacc[f][dt][0] *= al; oacc[f][dt][1] *= al;
                oacc[f][dt][2] *= ah; oacc[f][dt][3] *= ah;
            }
            // publish P rows for this frag
            int rl = r0 + f * 16 + g, rh = rl + 8;
#pragma unroll
            for (int nt = 0; nt < 8; nt++) {
                int c = nt * 8 + 2 * tg;
                *(float2*)&SP[rl * QP + c] = make_float2(tf32f(s[f][nt][0]), tf32f(s[f][nt][1]));
                *(float2*)&SP[rh * QP + c] = make_float2(tf32f(s[f][nt][2]), tf32f(s[f][nt][3]));
            }
        }

        CPWAIT1;              // V[kt] ready (K[kt+1] in flight)
        __syncthreads();

        // O += P V : LDSM P A-frags, scalar V B-frags (shared across m-frags)
#pragma unroll
        for (int ks = 0; ks < 8; ks++) {
            int kb = ks * 8;
            unsigned pa[2][4];
            ldsm4(pa[0], aSP[0] + ks * 32);
            ldsm4(pa[1], aSP[1] + ks * 32);
#pragma unroll
            for (int dt = 0; dt < 8; dt++) {
                unsigned bb[2];
                bb[0] = fu(VB[(kb + tg) * VP + dt * 8 + g]);
                bb[1] = fu(VB[(kb + tg + 4) * VP + dt * 8 + g]);
                mma8(oacc[0][dt], pa[0], bb);
                mma8(oacc[1][dt], pa[1], bb);
            }
        }
        __syncthreads();      // VB free before next V issue
    }

    // epilogue
    float* Og = g_O + ((size_t)(b * S_ + qt * QT_)) * D_ + h * DH_;
#pragma unroll
    for (int f = 0; f < 2; f++) {
        float il = 1.0f / lrow[f][0], ih = 1.0f / lrow[f][1];
        int rl = r0 + f * 16 + g, rh = rl + 8;
#pragma unroll
        for (int dt = 0; dt < 8; dt++) {
            int c = dt * 8 + 2 * tg;
            *(float2*)&Og[(size_t)rl * D_ + c] =
                make_float2(tf32f(oacc[f][dt][0] * il), tf32f(oacc[f][dt][1] * il));
            *(float2*)&Og[(size_t)rh * D_ + c] =
                make_float2(tf32f(oacc[f][dt][2] * ih), tf32f(oacc[f][dt][3] * ih));
        }
    }
}

// ---------------------------------------------------------------------------
// Output projection: g_O[16384,512] @ g_Wo^T + b_out -> out (fp32)
// ---------------------------------------------------------------------------
__global__ __launch_bounds__(256, 2) void out_kernel(const float* __restrict__ bias,
                                                     float* __restrict__ out) {
    extern __shared__ float sm[];
    float* As = sm;
    float* Bs = sm + 2*GST;

    int tid = threadIdx.x;
    int m0 = blockIdx.y * 128, n0 = blockIdx.x * 128;
    int w = tid >> 5, lane = tid & 31;
    int wm = w >> 1, wn = w & 1;
    int g = lane >> 2, tg = lane & 3;
    int lr = tid >> 3, lc4 = (tid & 7) * 4;
    int l8 = lane & 7, b3 = (lane >> 3) & 1, b4 = lane >> 4;

    const float* X = g_O;
    const float* W = g_Wo;

    unsigned aA[2], aB[4];
#pragma unroll
    for (int mt = 0; mt < 2; mt++)
        aA[mt] = sptr(As) + ((wm*32 + mt*16 + l8 + b3*8) * GP + b4*4) * 4;
#pragma unroll
    for (int p = 0; p < 4; p++)
        aB[p] = sptr(Bs) + ((wn*64 + (2*p + b4)*8 + l8) * GP + b3*4) * 4;

#define OUT_ISSUE(kc, stg) do {                                               \
        _Pragma("unroll")                                                     \
        for (int p = 0; p < 4; p++) {                                         \
            int row = lr + p * 32;                                            \
            CP16(sptr(&As[(stg)*GST + row*GP + lc4]),                         \
                 X + (size_t)(m0 + row) * D_ + (kc) + lc4);                   \
            CP16(sptr(&Bs[(stg)*GST + row*GP + lc4]),                         \
                 W + (size_t)(n0 + row) * D_ + (kc) + lc4);                   \
        }                                                                     \
        CPCOMMIT;                                                             \
    } while (0)

    OUT_ISSUE(0, 0);

    float acc[2][8][4];
#pragma unroll
    for (int mt = 0; mt < 2; mt++)
#pragma unroll
        for (int nt = 0; nt < 8; nt++)
#pragma unroll
            for (int i = 0; i < 4; i++) acc[mt][nt][i] = 0.f;

    for (int kci = 0; kci < 16; kci++) {
        int cur = kci & 1;
        if (kci + 1 < 16) { OUT_ISSUE((kci + 1) * 32, cur ^ 1); CPWAIT1; }
        else              { CPWAIT0; }
        __syncthreads();
        unsigned sb = cur * (GST * 4);
#pragma unroll
        for (int ks = 0; ks < 4; ks++) {
            unsigned kbb = sb + ks * 32;
            unsigned a0[4], a1[4];
            ldsm4(a0, aA[0] + kbb);
            ldsm4(a1, aA[1] + kbb);
#pragma unroll
            for (int p = 0; p < 4; p++) {
                unsigned bb[4];
                ldsm4(bb, aB[p] + kbb);
                mma8(acc[0][2*p],   a0, bb);
                mma8(acc[1][2*p],   a1, bb);
                mma8(acc[0][2*p+1], a0, bb + 2);
                mma8(acc[1][2*p+1], a1, bb + 2);
            }
        }
        __syncthreads();
    }

#pragma unroll
    for (int mt = 0; mt < 2; mt++) {
#pragma unroll
        for (int half = 0; half < 2; half++) {
            int mm = m0 + wm * 32 + mt * 16 + g + half * 8;
#pragma unroll
            for (int nt = 0; nt < 8; nt++) {
                int col = n0 + wn * 64 + nt * 8 + 2 * tg;
                float2 bi = *(const float2*)(bias + col);
                *(float2*)&out[(size_t)mm * D_ + col] =
                    make_float2(acc[mt][nt][half * 2 + 0] + bi.x,
                                acc[mt][nt][half * 2 + 1] + bi.y);
            }
        }
    }
}

// ---------------------------------------------------------------------------
extern "C" void kernel_launch(void* const* d_in, const int* in_sizes, int n_in,
                              void* d_out, int out_size) {
    const float* x     = (const float*)d_in[0];
    const float* w_in  = (const float*)d_in[1];
    const float* b_in  = (const float*)d_in[2];
    const float* w_out = (const float*)d_in[3];
    const float* b_out = (const float*)d_in[4];
    float* out = (float*)d_out;

    const int gemm_smem = 4 * GST * 4;                          // 73728 B
    const int attn_smem = (QT_*QP + 64*KP + 64*VP) * 4;         // 70656 B
    cudaFuncSetAttribute(qkv_kernel,  cudaFuncAttributeMaxDynamicSharedMemorySize, gemm_smem);
    cudaFuncSetAttribute(out_kernel,  cudaFuncAttributeMaxDynamicSharedMemorySize, gemm_smem);
    cudaFuncSetAttribute(attn_kernel, cudaFuncAttributeMaxDynamicSharedMemorySize, attn_smem);

    float* gx;  cudaGetSymbolAddress((void**)&gx,  g_X);
    float* gwi; cudaGetSymbolAddress((void**)&gwi, g_Wi);
    float* gwo; cudaGetSymbolAddress((void**)&gwo, g_Wo);
    round_kernel<<<(M_*D_/4 + 255)/256, 256>>>((const float4*)x,     (float4*)gx,  M_*D_/4);
    round_kernel<<<(3*D_*D_/4 + 255)/256, 256>>>((const float4*)w_in,  (float4*)gwi, 3*D_*D_/4);
    round_kernel<<<(D_*D_/4 + 255)/256, 256>>>((const float4*)w_out, (float4*)gwo, D_*D_/4);

    qkv_kernel<<<dim3(12, 128), 256, gemm_smem>>>(b_in);
    attn_kernel<<<dim3(S_ / QT_, H_, B_), 128, attn_smem>>>();
    out_kernel<<<dim3(4, 128), 256, gemm_smem>>>(b_out, out);
}